// round 11
// baseline (speedup 1.0000x reference)
#include <cuda_runtime.h>
#include <cstdint>

#define BB 32
#define CC 128
#define HH 56
#define WW 56

// ---------------- scratch (module-static device memory; no allocs) ----------------
__device__ uint8_t g_ah[BB * HH * WW * CC];   // u8 high acts, NHWC (128 B/pixel)
__device__ uint8_t g_al[BB * HH * WW * CC];   // u8 low  acts, NHWC (128 B/pixel)
__device__ int8_t  g_wh[CC * 9 * CC];         // s8 high weights [co][k][ci] (mma path)
__device__ int8_t  g_wlT[9 * 2 * 32 * 64 * 4];// s8 low weights [k][ch][ci4][co(64)][ci&3]
__device__ uint8_t g_mask[BB * 7 * 7 * CC];   // pooled mask [b][bh][bw][c]
__device__ float   g_fsh[CC];                 // fused scale high
__device__ float   g_fsl[CC];                 // fused scale low

__device__ __forceinline__ int dp4a_us(unsigned a, unsigned b, int c) {
    int r;
    asm("dp4a.u32.s32 %0, %1, %2, %3;" : "=r"(r) : "r"(a), "r"(b), "r"(c));
    return r;
}

// ---------------- K1: per-output-channel weight quantization ----------------
__global__ __launch_bounds__(256) void quant_weights_kernel(
    const float* __restrict__ w, const float* __restrict__ as_ptr,
    float nlev, int which)
{
    int co = blockIdx.x;
    int tid = threadIdx.x;
    const float* wc = w + co * (CC * 9);

    float mx = 0.f;
    for (int i = tid; i < CC * 9; i += 256) mx = fmaxf(mx, fabsf(wc[i]));
    __shared__ float red[256];
    red[tid] = mx;
    __syncthreads();
    for (int s = 128; s > 0; s >>= 1) {
        if (tid < s) red[tid] = fmaxf(red[tid], red[tid + s]);
        __syncthreads();
    }
    float s = red[0] / nlev;

    int ch = co >> 6, c64 = co & 63;

    for (int i = tid; i < CC * 9; i += 256) {
        float q = rintf(wc[i] / s);
        q = fminf(fmaxf(q, -nlev), nlev);
        int ci = i / 9, k = i % 9;                 // OIHW: i = ci*9 + k
        if (which == 0) {
            g_wh[(co * 9 + k) * CC + ci] = (int8_t)q;
        } else {
            int ci4 = ci >> 2;
            int word = ((k * 2 + ch) * 32 + ci4) * 64 + c64;
            g_wlT[word * 4 + (ci & 3)] = (int8_t)q;
        }
    }
    if (tid == 0) {
        if (which) g_fsl[co] = s * as_ptr[0];
        else       g_fsh[co] = s * as_ptr[0];
    }
}

// ---------------- K2a: pooled predictor mask ----------------
// grid (7 bh, BB). Warp handles 16 channels; coalesced row reads + shfl reduce.
__global__ __launch_bounds__(256) void pool_mask_kernel(const float* __restrict__ x)
{
    int bh = blockIdx.x, b = blockIdx.y;
    int warp = threadIdx.x >> 5, lane = threadIdx.x & 31;

    for (int ci = 0; ci < 16; ci++) {
        int c = ci * 8 + warp;
        const float* xp = x + ((size_t)(b * CC + c)) * (HH * WW) + bh * 8 * WW;
        float sa = 0.f, sb = 0.f;
        #pragma unroll
        for (int r = 0; r < 8; r++) {
            sa += xp[r * WW + lane];
            if (lane < 24) sb += xp[r * WW + 32 + lane];
        }
        sa += __shfl_xor_sync(~0u, sa, 1);
        sa += __shfl_xor_sync(~0u, sa, 2);
        sa += __shfl_xor_sync(~0u, sa, 4);
        sb += __shfl_xor_sync(~0u, sb, 1);
        sb += __shfl_xor_sync(~0u, sb, 2);
        sb += __shfl_xor_sync(~0u, sb, 4);
        if ((lane & 7) == 0) {
            int bw = lane >> 3;
            uint8_t* mp = g_mask + ((b * 7 + bh) * 7) * CC + c;
            mp[bw * CC] = (sa * (1.0f / 64.0f) >= 0.05f) ? 1 : 0;
            if (bw < 3)
                mp[(bw + 4) * CC] = (sb * (1.0f / 64.0f) >= 0.05f) ? 1 : 0;
        }
    }
}

// ---------------- K2b: activation fake-quant -> NHWC uint8 (coalesced both sides) ----------------
// grid (HH, BB): one (b,h) row per block. smem transpose [p][c] stride 132.
__global__ __launch_bounds__(256) void act_quant_kernel(
    const float* __restrict__ x,
    const float* __restrict__ ash_p, const float* __restrict__ asl_p)
{
    __shared__ float sx[WW * 132];
    __shared__ uint8_t sm[7 * CC];
    int h = blockIdx.x, b = blockIdx.y;
    int tid = threadIdx.x;

    const float* xrow = x + (size_t)b * CC * (HH * WW) + h * WW;
    for (int i = tid; i < CC * WW; i += 256) {
        int c = i / WW, p = i - c * WW;
        sx[p * 132 + c] = xrow[(size_t)c * (HH * WW) + p];
    }
    const uint8_t* gm = g_mask + ((b * 7 + (h >> 3)) * 7) * CC;
    for (int i = tid; i < 7 * CC; i += 256) sm[i] = gm[i];
    __syncthreads();

    float ash = ash_p[0], asl = asl_p[0];
    #pragma unroll 1
    for (int it = 0; it < 7; it++) {
        int idx = it * 256 + tid;
        int p = idx >> 5, c4 = idx & 31;
        const float* vp = &sx[p * 132 + c4 * 4];
        const uint8_t* mp = &sm[(p >> 3) * CC + c4 * 4];
        unsigned qh = 0u, ql = 0u;
        #pragma unroll
        for (int j = 0; j < 4; j++) {
            float v = vp[j];
            bool m = mp[j] != 0;
            float fh = fminf(fmaxf(rintf(v / ash), 0.f), 255.f);
            float fl = fminf(fmaxf(rintf(v / asl), 0.f), 15.f);
            unsigned b8h = m ? (unsigned)fh : 0u;
            unsigned b8l = m ? 0u : (unsigned)fl;
            qh |= b8h << (8 * j);
            ql |= b8l << (8 * j);
        }
        int base = ((b * HH + h) * WW + p) * (CC / 4) + c4;
        ((unsigned*)g_ah)[base] = qh;
        ((unsigned*)g_al)[base] = ql;
    }
}

// ---------------- K3: hybrid conv3x3 — high via mma+ldmatrix, low via dp4a ----------------
// CTA: 256 thr, 8 warps (4M x 2N), tile 64 pix x 64 co, 3 CTAs/SM.
// dp4a lanes transposed: lane=co, loop pixels; weights via fully-dense LDS.32
// (1 wavefront/ci4), acts via uniform-address broadcast LDS.128 (1 wavefront).

#define ROWB 144
#define ACT_H_OFF 0
#define ACT_L_OFF 14400                         // 100*144
#define WH_OFF 28800
#define WH_BUF 9216                             // 64co * 144
#define WL_OFF (28800 + 2 * 9216)               // 47232
#define WL_BUF 8192                             // 32 ci4 * 64 co * 4B
#define CONV_SMEM (WL_OFF + 2 * WL_BUF)         // 63616
// epilogue exchange buffer: reuses [WH_OFF .. WH_OFF+16640) after last tap

__device__ __forceinline__ void mma_u8s8(int* c, const unsigned* a, unsigned b0, unsigned b1) {
    asm volatile(
        "mma.sync.aligned.m16n8k32.row.col.s32.u8.s8.s32 "
        "{%0,%1,%2,%3}, {%4,%5,%6,%7}, {%8,%9}, {%0,%1,%2,%3};"
        : "+r"(c[0]), "+r"(c[1]), "+r"(c[2]), "+r"(c[3])
        : "r"(a[0]), "r"(a[1]), "r"(a[2]), "r"(a[3]), "r"(b0), "r"(b1));
}

__device__ __forceinline__ void ldsm_x4(unsigned addr, unsigned* r) {
    asm volatile(
        "ldmatrix.sync.aligned.m8n8.x4.shared.b16 {%0,%1,%2,%3}, [%4];"
        : "=r"(r[0]), "=r"(r[1]), "=r"(r[2]), "=r"(r[3]) : "r"(addr));
}

__device__ __forceinline__ void stage_weights(char* smem, int buf, int k, int co0, int tid) {
    unsigned sb = (unsigned)__cvta_generic_to_shared(smem);
    int ch = co0 >> 6;
    #pragma unroll
    for (int j = 0; j < 4; j++) {
        int i = tid + j * 256;
        if (i < 512) {
            // high mma weights: 64 co x 8 c16
            int co = i >> 3, c16 = i & 7;
            const char* src = (const char*)g_wh + ((co0 + co) * 9 + k) * CC + c16 * 16;
            unsigned d = sb + WH_OFF + buf * WH_BUF + co * ROWB + c16 * 16;
            asm volatile("cp.async.cg.shared.global [%0], [%1], 16;" :: "r"(d), "l"(src));
        } else {
            // low dp4a weights: contiguous 8KB slice [ci4][64co]
            int r = i - 512;
            const char* src = (const char*)g_wlT + (k * 2 + ch) * 8192 + r * 16;
            unsigned d = sb + WL_OFF + buf * WL_BUF + r * 16;
            asm volatile("cp.async.cg.shared.global [%0], [%1], 16;" :: "r"(d), "l"(src));
        }
    }
}

__global__ __launch_bounds__(256, 3) void conv_hybrid_kernel(float* __restrict__ out)
{
    extern __shared__ __align__(16) char smem[];
    unsigned sb32 = (unsigned)__cvta_generic_to_shared(smem);

    int tid = threadIdx.x;
    int bz = blockIdx.z;
    int b = bz >> 1;
    int co0 = (bz & 1) * 64;
    int h0 = blockIdx.y * 8, w0 = blockIdx.x * 8;

    // act halo tiles (both convs): 1600 16B chunks; invalid -> zero store
    #pragma unroll
    for (int j = 0; j < 7; j++) {
        int i = tid + j * 256;
        if (i < 1600) {
            int cv = i / 800, r = i % 800;
            int p = r >> 3, c16 = r & 7;
            int pr = p / 10 - 1 + h0, pc = p % 10 - 1 + w0;
            char* dgen = smem + (cv ? ACT_L_OFF : ACT_H_OFF) + p * ROWB + c16 * 16;
            if (pr >= 0 && pr < HH && pc >= 0 && pc < WW) {
                const char* src = (const char*)(cv ? g_al : g_ah)
                                  + ((size_t)((b * HH + pr) * WW + pc)) * 128 + c16 * 16;
                unsigned d = (unsigned)__cvta_generic_to_shared(dgen);
                asm volatile("cp.async.cg.shared.global [%0], [%1], 16;" :: "r"(d), "l"(src));
            } else {
                *(uint4*)dgen = make_uint4(0u, 0u, 0u, 0u);
            }
        }
    }
    stage_weights(smem, 0, 0, co0, tid);
    asm volatile("cp.async.commit_group;" ::: "memory");

    int lane = tid & 31, warp = tid >> 5;
    int wm = warp >> 1;          // 0..3 : 16-pixel group (rows 2wm, 2wm+1)
    int wn = warp & 1;           // 0..1 : 32-co group
    int g = lane >> 2, t = lane & 3;

    // ldmatrix lane roles (A operand)
    int lg = lane & 7;
    int rsel = (lane >> 3) & 1;
    int hi16 = (lane >> 4) & 1;

    int acch[4][4];              // mma accum [nt][e]
    int accl[16];                // dp4a accum: pixel i, co = co0 + wn*32 + lane
    #pragma unroll
    for (int nt = 0; nt < 4; nt++)
        #pragma unroll
        for (int q = 0; q < 4; q++) acch[nt][q] = 0;
    #pragma unroll
    for (int i = 0; i < 16; i++) accl[i] = 0;

    const char* s_al = smem + ACT_L_OFF;
    unsigned bRow = sb32 + WH_OFF + (unsigned)(wn * 32 + lane) * ROWB;
    int wlane = wn * 32 + lane;

    #pragma unroll 1
    for (int k9 = 0; k9 < 9; k9++) {
        asm volatile("cp.async.wait_group 0;" ::: "memory");
        __syncthreads();
        int buf = k9 & 1;
        if (k9 < 8) {
            stage_weights(smem, buf ^ 1, k9 + 1, co0, tid);
            asm volatile("cp.async.commit_group;" ::: "memory");
        }
        int kh = k9 / 3, kw = k9 - kh * 3;

        // ---- high conv: tensor pipe, fragments via LDSM ----
        unsigned aAddr = sb32 + ACT_H_OFF
                       + (unsigned)(((2 * wm + kh) * 10 + lg + kw + 10 * rsel) * ROWB)
                       + (unsigned)(hi16 * 16);
        unsigned bAddr = bRow + (unsigned)(buf * WH_BUF);
        #pragma unroll
        for (int chunk = 0; chunk < 4; chunk++) {
            unsigned a[4], bA[4], bB[4];
            ldsm_x4(aAddr + chunk * 32, a);
            ldsm_x4(bAddr + chunk * 32, bA);
            ldsm_x4(bAddr + chunk * 32 + 16, bB);
            #pragma unroll
            for (int nt = 0; nt < 4; nt++)
                mma_u8s8(acch[nt], a, bA[nt], bB[nt]);
        }

        // ---- low conv: fma pipe (dp4a), transposed lanes ----
        const unsigned* wl = (const unsigned*)(smem + WL_OFF + buf * WL_BUF);
        #pragma unroll
        for (int half = 0; half < 2; half++) {
            unsigned wreg[16];
            #pragma unroll
            for (int j = 0; j < 16; j++)
                wreg[j] = wl[(half * 16 + j) * 64 + wlane];
            #pragma unroll
            for (int i = 0; i < 16; i++) {
                int pin = (2 * wm + (i >> 3) + kh) * 10 + (i & 7) + kw;
                const uint4* ap = (const uint4*)(s_al + pin * ROWB + half * 64);
                #pragma unroll
                for (int s4 = 0; s4 < 4; s4++) {
                    uint4 a = ap[s4];
                    accl[i] = dp4a_us(a.x, wreg[s4 * 4 + 0], accl[i]);
                    accl[i] = dp4a_us(a.y, wreg[s4 * 4 + 1], accl[i]);
                    accl[i] = dp4a_us(a.z, wreg[s4 * 4 + 2], accl[i]);
                    accl[i] = dp4a_us(a.w, wreg[s4 * 4 + 3], accl[i]);
                }
            }
        }
    }

    // ---- exchange accl into mma fragment layout via smem ----
    __syncthreads();                                  // weight reads done
    int* sacc = (int*)(smem + WH_OFF);                // [64 pix][65]
    #pragma unroll
    for (int i = 0; i < 16; i++)
        sacc[(wm * 16 + i) * 65 + wlane] = accl[i];
    __syncthreads();

    // epilogue: y = fsh*acc_h + fsl*acc_l -> NCHW fp32
    int p0 = wm * 16 + g;
    int oh0 = h0 + (p0 >> 3), ow = w0 + (p0 & 7);
    int oh1 = oh0 + 1;
    #pragma unroll
    for (int nt = 0; nt < 4; nt++) {
        int cl = wn * 32 + nt * 8 + t * 2;            // CTA-local co
        int cg0 = co0 + cl;
        float sh0 = g_fsh[cg0],     sl0 = g_fsl[cg0];
        float sh1 = g_fsh[cg0 + 1], sl1 = g_fsl[cg0 + 1];
        int l00 = sacc[(wm * 16 + g) * 65 + cl];
        int l01 = sacc[(wm * 16 + g) * 65 + cl + 1];
        int l10 = sacc[(wm * 16 + 8 + g) * 65 + cl];
        int l11 = sacc[(wm * 16 + 8 + g) * 65 + cl + 1];
        out[((b * CC + cg0) * HH + oh0) * WW + ow] =
            sh0 * (float)acch[nt][0] + sl0 * (float)l00;
        out[((b * CC + cg0 + 1) * HH + oh0) * WW + ow] =
            sh1 * (float)acch[nt][1] + sl1 * (float)l01;
        out[((b * CC + cg0) * HH + oh1) * WW + ow] =
            sh0 * (float)acch[nt][2] + sl0 * (float)l10;
        out[((b * CC + cg0 + 1) * HH + oh1) * WW + ow] =
            sh1 * (float)acch[nt][3] + sl1 * (float)l11;
    }
}

// ---------------- launch ----------------
extern "C" void kernel_launch(void* const* d_in, const int* in_sizes, int n_in,
                              void* d_out, int out_size)
{
    const float* x      = (const float*)d_in[0];
    const float* w_high = (const float*)d_in[1];
    const float* w_low  = (const float*)d_in[2];
    const float* as_h   = (const float*)d_in[3];
    const float* as_l   = (const float*)d_in[4];
    float* out = (float*)d_out;

    cudaFuncSetAttribute(conv_hybrid_kernel,
                         cudaFuncAttributeMaxDynamicSharedMemorySize, CONV_SMEM);

    quant_weights_kernel<<<CC, 256>>>(w_high, as_h, 127.0f, 0);
    quant_weights_kernel<<<CC, 256>>>(w_low,  as_l,   7.0f, 1);
    pool_mask_kernel<<<dim3(7, BB), 256>>>(x);
    act_quant_kernel<<<dim3(HH, BB), 256>>>(x, as_h, as_l);
    conv_hybrid_kernel<<<dim3(WW / 8, HH / 8, BB * 2), 256, CONV_SMEM>>>(out);
}